// round 2
// baseline (speedup 1.0000x reference)
#include <cuda_runtime.h>
#include <cstdint>

// Problem constants (fixed by the reference):
//   B=64 batches, R=32 rows, N=16384 context nodes, D=64 dim, O=8 types.
//
// Key identity: avg_sim[b,r] = dot(norm_l[b,r], S[b]) / nvalid[b]
//   where S[b] = sum over valid n of l2norm(h_context[b,n]).
// fmask density ~0.75%, so we skip reading h_context rows whose mask is 0.
//
// R1 finding: harness widens bool inputs to int32 (rel_err was exactly 3.0 ==
// the 4x-undercount signature of reading int32 masks as bytes).

#define BB 64
#define RR 32
#define NCTX 16384
#define DD 64
#define OO 8

#define CHUNK 2048
#define NCHUNKS (NCTX / CHUNK)   // 8 -> grid 512 blocks

// Allocation-free scratch (harness forbids cudaMalloc).
__device__ float g_S[BB][DD];
__device__ float g_cnt[BB];

// ---------------------------------------------------------------------------
// Kernel 0: zero the scratch accumulators.
// ---------------------------------------------------------------------------
__global__ void zero_scratch_kernel() {
    int i = blockIdx.x * blockDim.x + threadIdx.x;
    if (i < BB * DD) reinterpret_cast<float*>(g_S)[i] = 0.0f;
    if (i < BB)      g_cnt[i] = 0.0f;
}

// ---------------------------------------------------------------------------
// Kernel 1: per-(b,chunk) block. Phase 1: scan masks (int32, vectorized as
// int4), collect valid indices into smem. Phase 2: warps gather +
// l2-normalize only the valid h_context rows and accumulate into S[b]/cnt[b].
// ---------------------------------------------------------------------------
__global__ __launch_bounds__(256) void gather_accum_kernel(
    const float* __restrict__ hctx,       // [B, N, D]
    const int*  __restrict__ o_types,     // [B, N]
    const int*  __restrict__ center_o,    // [B]
    const int*  __restrict__ adj,         // [B, N] bool widened to int32
    const int*  __restrict__ two_hop)     // [B, N] bool widened to int32
{
    const int b     = blockIdx.x / NCHUNKS;
    const int chunk = blockIdx.x % NCHUNKS;
    const int n0    = chunk * CHUNK;
    const int ctr   = center_o[b];

    __shared__ int   s_idx[CHUNK];
    __shared__ int   s_cnt;
    __shared__ float s_acc[DD];

    if (threadIdx.x == 0) s_cnt = 0;
    if (threadIdx.x < DD) s_acc[threadIdx.x] = 0.0f;
    __syncthreads();

    // Phase 1: vectorized mask scan. CHUNK/4 = 512 int4's, 256 threads x2.
    const long base4 = ((long)b * NCTX + n0) >> 2;   // int4 index
    const int4* ot4 = reinterpret_cast<const int4*>(o_types) + base4;
    const int4* aj4 = reinterpret_cast<const int4*>(adj)     + base4;
    const int4* th4 = reinterpret_cast<const int4*>(two_hop) + base4;

    #pragma unroll
    for (int it = 0; it < CHUNK / 4 / 256; ++it) {
        int q = it * 256 + threadIdx.x;              // int4 index within chunk
        int4 t = ot4[q];
        int4 a = aj4[q];
        int4 h = th4[q];
        int m0 = (t.x == ctr) & ((a.x | h.x) != 0);
        int m1 = (t.y == ctr) & ((a.y | h.y) != 0);
        int m2 = (t.z == ctr) & ((a.z | h.z) != 0);
        int m3 = (t.w == ctr) & ((a.w | h.w) != 0);
        int cnt = m0 + m1 + m2 + m3;
        if (cnt) {
            int p = atomicAdd(&s_cnt, cnt);
            int nb = n0 + q * 4;
            if (m0) s_idx[p++] = nb + 0;
            if (m1) s_idx[p++] = nb + 1;
            if (m2) s_idx[p++] = nb + 2;
            if (m3) s_idx[p]   = nb + 3;
        }
    }
    __syncthreads();
    const int cnt = s_cnt;

    // Phase 2: warp-per-row gather + normalize + accumulate.
    const int wid  = threadIdx.x >> 5;
    const int lane = threadIdx.x & 31;
    float a0 = 0.0f, a1 = 0.0f;

    for (int i = wid; i < cnt; i += 8) {
        const float2* row = reinterpret_cast<const float2*>(
            hctx + ((size_t)b * NCTX + (size_t)s_idx[i]) * DD);
        float2 v = row[lane];                       // lane covers cols 2*lane, 2*lane+1
        float sq = v.x * v.x + v.y * v.y;
        #pragma unroll
        for (int o = 16; o; o >>= 1) sq += __shfl_xor_sync(0xffffffffu, sq, o);
        float rs = rsqrtf(fmaxf(sq, 1e-12f));       // matches tf.nn.l2_normalize eps
        a0 += v.x * rs;
        a1 += v.y * rs;
    }

    // Per-warp partials -> shared (8-deep atomic max per address).
    atomicAdd(&s_acc[lane * 2 + 0], a0);
    atomicAdd(&s_acc[lane * 2 + 1], a1);
    __syncthreads();

    if (cnt > 0) {
        if (threadIdx.x < DD) atomicAdd(&g_S[b][threadIdx.x], s_acc[threadIdx.x]);
        if (threadIdx.x == 0) atomicAdd(&g_cnt[b], (float)cnt);
    }
}

// ---------------------------------------------------------------------------
// Kernel 2: epilogue. One block per b; warp per r (4 r's per warp).
// avg = dot(l2norm(l_local[b,r]), S[b]) / max(nv, 1e-9)
// out = relu(lambda_so[r, ctr] / max(nv, 1)) * (1 - avg)
// ---------------------------------------------------------------------------
__global__ __launch_bounds__(256) void finish_kernel(
    const float* __restrict__ l_local,     // [B, R, D]
    const float* __restrict__ lambda_so,   // [R, O]
    const int*   __restrict__ center_o,    // [B]
    float* __restrict__ out)               // [B, R]
{
    const int b    = blockIdx.x;
    const int wid  = threadIdx.x >> 5;
    const int lane = threadIdx.x & 31;

    const float nv  = g_cnt[b];
    const int   ctr = center_o[b];
    const float2 Sv = reinterpret_cast<const float2*>(g_S[b])[lane];

    const float inv_nv_sim = 1.0f / fmaxf(nv, 1e-9f);
    const float inv_nv_lam = 1.0f / fmaxf(nv, 1.0f);

    for (int r = wid; r < RR; r += 8) {
        const float2* row = reinterpret_cast<const float2*>(
            l_local + ((size_t)b * RR + r) * DD);
        float2 v = row[lane];
        float sq = v.x * v.x + v.y * v.y;
        float dp = v.x * Sv.x + v.y * Sv.y;
        #pragma unroll
        for (int o = 16; o; o >>= 1) {
            sq += __shfl_xor_sync(0xffffffffu, sq, o);
            dp += __shfl_xor_sync(0xffffffffu, dp, o);
        }
        float rs  = rsqrtf(fmaxf(sq, 1e-12f));
        float avg = dp * rs * inv_nv_sim;
        float lam = lambda_so[r * OO + ctr];
        float w   = fmaxf(lam * inv_nv_lam, 0.0f) * (1.0f - avg);
        if (lane == 0) out[(size_t)b * RR + r] = w;
    }
}

// ---------------------------------------------------------------------------
// Launch wrapper. Inputs per metadata order:
//   0: l_local   f32 [B,R,D]
//   1: h_context f32 [B,N,D]
//   2: lambda_so f32 [R,O]
//   3: center_o  i32 [B]
//   4: o_types   i32 [B,N]
//   5: adj_mask  bool->i32 [B,N]
//   6: two_hop_mask bool->i32 [B,N]
// Output: f32 [B,R]
// ---------------------------------------------------------------------------
extern "C" void kernel_launch(void* const* d_in, const int* in_sizes, int n_in,
                              void* d_out, int out_size) {
    const float* l_local   = (const float*)d_in[0];
    const float* h_context = (const float*)d_in[1];
    const float* lambda_so = (const float*)d_in[2];
    const int*   center_o  = (const int*)d_in[3];
    const int*   o_types   = (const int*)d_in[4];
    const int*   adj       = (const int*)d_in[5];
    const int*   two_hop   = (const int*)d_in[6];
    float* out = (float*)d_out;

    zero_scratch_kernel<<<(BB * DD + 255) / 256, 256>>>();
    gather_accum_kernel<<<BB * NCHUNKS, 256>>>(h_context, o_types, center_o,
                                               adj, two_hop);
    finish_kernel<<<BB, 256>>>(l_local, lambda_so, center_o, out);
}